// round 12
// baseline (speedup 1.0000x reference)
#include <cuda_runtime.h>
#include <cuda_bf16.h>
#include <cstdint>

// Newton-Schulz iterative inverse, fully shared-memory resident.
// One CTA per 128x128 matrix. 256 threads, 8x8 register tile per thread,
// packed f32x2 FMAs for 2x fp32 throughput.

#define LDIM 132              // padded row stride (floats): multiple of 4, != 0 mod 128
#define TILE_FLOATS (128 * LDIM)
#define SMEM_FLOATS (3 * TILE_FLOATS + 256)
#define SMEM_BYTES (SMEM_FLOATS * 4)

// ---------- packed fp32x2 helpers ----------
__device__ __forceinline__ unsigned long long pack_dup(float a) {
    unsigned long long r;
    asm("mov.b64 %0, {%1, %1};" : "=l"(r) : "f"(a));
    return r;
}
__device__ __forceinline__ unsigned long long pack2(float a, float b) {
    unsigned long long r;
    asm("mov.b64 %0, {%1, %2};" : "=l"(r) : "f"(a), "f"(b));
    return r;
}
__device__ __forceinline__ void ffma2(unsigned long long& acc,
                                      unsigned long long a,
                                      unsigned long long b) {
    asm("fma.rn.f32x2 %0, %1, %2, %0;" : "+l"(acc) : "l"(a), "l"(b));
}
__device__ __forceinline__ float2 unpack2(unsigned long long v) {
    float2 f;
    asm("mov.b64 {%0, %1}, %2;" : "=f"(f.x), "=f"(f.y) : "l"(v));
    return f;
}

// ---------- 128x128x128 GEMM, all operands in shared memory ----------
// O = L @ R            (TWO_I_MINUS = false)
// O = 2I - L @ R       (TWO_I_MINUS = true)
// Safe for O == L (in-place): all reads of L happen before the internal
// __syncthreads(); each thread only reads/writes the rows it owns.
template <bool TWO_I_MINUS>
__device__ __forceinline__ void gemm128(const float* L, const float* R,
                                        float* O, int tx, int ty) {
    unsigned long long acc[8][4];
#pragma unroll
    for (int i = 0; i < 8; i++)
#pragma unroll
        for (int j = 0; j < 4; j++) acc[i][j] = 0ULL;  // (0.0f, 0.0f)

    // Rows owned by this thread: 4*ty + i (i<4), 64 + 4*ty + (i-4) (i>=4)
    // Cols owned:                4*tx + j (j<4), 64 + 4*tx + (j-4)
    const float* l0 = L + (4 * ty) * LDIM;
    const float* r0 = R + 4 * tx;

#pragma unroll 2
    for (int k = 0; k < 128; k++) {
        const float* rk = r0 + k * LDIM;
        float4 b0 = *(const float4*)(rk);
        float4 b1 = *(const float4*)(rk + 64);
        unsigned long long bd0 = pack2(b0.x, b0.y);
        unsigned long long bd1 = pack2(b0.z, b0.w);
        unsigned long long bd2 = pack2(b1.x, b1.y);
        unsigned long long bd3 = pack2(b1.z, b1.w);
#pragma unroll
        for (int i = 0; i < 8; i++) {
            const int ro = ((i < 4) ? i : (60 + i)) * LDIM;  // 60+i = 64+(i-4)
            unsigned long long ad = pack_dup(l0[ro + k]);
            ffma2(acc[i][0], ad, bd0);
            ffma2(acc[i][1], ad, bd1);
            ffma2(acc[i][2], ad, bd2);
            ffma2(acc[i][3], ad, bd3);
        }
    }

    __syncthreads();  // all reads of L complete before (possibly aliased) writes

#pragma unroll
    for (int i = 0; i < 8; i++) {
        const int r = (i < 4) ? (4 * ty + i) : (64 + 4 * ty + (i - 4));
        float* orow = O + r * LDIM;
#pragma unroll
        for (int h = 0; h < 2; h++) {
            const int cbase = (h == 0) ? (4 * tx) : (64 + 4 * tx);
            float2 p0 = unpack2(acc[i][2 * h]);
            float2 p1 = unpack2(acc[i][2 * h + 1]);
            float v0 = p0.x, v1 = p0.y, v2 = p1.x, v3 = p1.y;
            if (TWO_I_MINUS) {
                v0 = ((r == cbase + 0) ? 2.0f : 0.0f) - v0;
                v1 = ((r == cbase + 1) ? 2.0f : 0.0f) - v1;
                v2 = ((r == cbase + 2) ? 2.0f : 0.0f) - v2;
                v3 = ((r == cbase + 3) ? 2.0f : 0.0f) - v3;
            }
            *(float4*)(orow + cbase) = make_float4(v0, v1, v2, v3);
        }
    }
}

extern __shared__ float smem[];

__global__ void __launch_bounds__(256, 1)
newton_schulz_inverse_kernel(const float* __restrict__ W,
                             const int* __restrict__ num_iters,
                             float* __restrict__ out) {
    float* sW = smem;
    float* sX = sW + TILE_FLOATS;
    float* sT = sX + TILE_FLOATS;
    float* red = sT + TILE_FLOATS;

    const int tid = threadIdx.x;
    const int bid = blockIdx.x;
    const float* Wg = W + (size_t)bid * 16384;

    // ---- load W (padded, float4) ----
    for (int idx = tid; idx < 4096; idx += 256) {
        int r = idx >> 5, c4 = (idx & 31) << 2;
        float4 v = *(const float4*)(Wg + r * 128 + c4);
        *(float4*)(sW + r * LDIM + c4) = v;
    }
    __syncthreads();

    // ---- norms: norminf = max row |sum|, norm1 = max col |sum| ----
    if (tid < 128) {
        float rs = 0.0f, cs = 0.0f;
        for (int c = 0; c < 128; c++) {
            rs += fabsf(sW[tid * LDIM + c]);  // row tid
            cs += fabsf(sW[c * LDIM + tid]);  // col tid
        }
        red[tid] = rs;
        red[128 + tid] = cs;
    }
    __syncthreads();
    float ninf = 0.0f, n1 = 0.0f;
    for (int t = 0; t < 128; t++) {
        ninf = fmaxf(ninf, red[t]);
        n1 = fmaxf(n1, red[128 + t]);
    }
    const float rscale = 1.0f / (n1 * ninf);

    // ---- X0 = W^T * rscale ----
    for (int idx = tid; idx < 16384; idx += 256) {
        int r = idx >> 7, c = idx & 127;
        sX[c * LDIM + r] = sW[r * LDIM + c] * rscale;
    }
    __syncthreads();

    // ---- Newton-Schulz iterations ----
    const int tx = tid & 15, ty = tid >> 4;
    const int ni = *num_iters;
    for (int it = 0; it < ni; it++) {
        gemm128<true>(sW, sX, sT, tx, ty);   // T = 2I - W @ X
        __syncthreads();
        gemm128<false>(sX, sT, sX, tx, ty);  // X = X @ T  (in-place, row-safe)
        __syncthreads();
    }

    // ---- store result ----
    float* Og = out + (size_t)bid * 16384;
    for (int idx = tid; idx < 4096; idx += 256) {
        int r = idx >> 5, c4 = (idx & 31) << 2;
        *(float4*)(Og + r * 128 + c4) = *(const float4*)(sX + r * LDIM + c4);
    }
}

extern "C" void kernel_launch(void* const* d_in, const int* in_sizes, int n_in,
                              void* d_out, int out_size) {
    const float* W = (const float*)d_in[0];
    const int* num_iters = (const int*)d_in[1];
    float* out = (float*)d_out;

    const int nmat = in_sizes[0] >> 14;  // elements / (128*128)

    cudaFuncSetAttribute(newton_schulz_inverse_kernel,
                         cudaFuncAttributeMaxDynamicSharedMemorySize, SMEM_BYTES);

    newton_schulz_inverse_kernel<<<nmat, 256, SMEM_BYTES>>>(W, num_iters, out);
}

// round 13
// speedup vs baseline: 1.0022x; 1.0022x over previous
#include <cuda_runtime.h>
#include <cuda_bf16.h>
#include <cstdint>

// Newton-Schulz iterative inverse, fully shared-memory resident.
// One CTA per 128x128 matrix. 256 threads, 8x8 register tile per thread,
// packed f32x2 FMAs for 2x fp32 throughput.

#define LDIM 132              // padded row stride (floats): multiple of 4, != 0 mod 128
#define TILE_FLOATS (128 * LDIM)
#define SMEM_FLOATS (3 * TILE_FLOATS + 256)
#define SMEM_BYTES (SMEM_FLOATS * 4)

// ---------- packed fp32x2 helpers ----------
__device__ __forceinline__ unsigned long long pack_dup(float a) {
    unsigned long long r;
    asm("mov.b64 %0, {%1, %1};" : "=l"(r) : "f"(a));
    return r;
}
__device__ __forceinline__ unsigned long long pack2(float a, float b) {
    unsigned long long r;
    asm("mov.b64 %0, {%1, %2};" : "=l"(r) : "f"(a), "f"(b));
    return r;
}
__device__ __forceinline__ void ffma2(unsigned long long& acc,
                                      unsigned long long a,
                                      unsigned long long b) {
    asm("fma.rn.f32x2 %0, %1, %2, %0;" : "+l"(acc) : "l"(a), "l"(b));
}
__device__ __forceinline__ float2 unpack2(unsigned long long v) {
    float2 f;
    asm("mov.b64 {%0, %1}, %2;" : "=f"(f.x), "=f"(f.y) : "l"(v));
    return f;
}

// ---------- 128x128x128 GEMM, all operands in shared memory ----------
// O = L @ R            (TWO_I_MINUS = false)
// O = 2I - L @ R       (TWO_I_MINUS = true)
// Safe for O == L (in-place): all reads of L happen before the internal
// __syncthreads(); each thread only reads/writes the rows it owns.
template <bool TWO_I_MINUS>
__device__ __forceinline__ void gemm128(const float* L, const float* R,
                                        float* O, int tx, int ty) {
    unsigned long long acc[8][4];
#pragma unroll
    for (int i = 0; i < 8; i++)
#pragma unroll
        for (int j = 0; j < 4; j++) acc[i][j] = 0ULL;  // (0.0f, 0.0f)

    // Rows owned by this thread: 4*ty + i (i<4), 64 + 4*ty + (i-4) (i>=4)
    // Cols owned:                4*tx + j (j<4), 64 + 4*tx + (j-4)
    const float* l0 = L + (4 * ty) * LDIM;
    const float* r0 = R + 4 * tx;

#pragma unroll 2
    for (int k = 0; k < 128; k++) {
        const float* rk = r0 + k * LDIM;
        float4 b0 = *(const float4*)(rk);
        float4 b1 = *(const float4*)(rk + 64);
        unsigned long long bd0 = pack2(b0.x, b0.y);
        unsigned long long bd1 = pack2(b0.z, b0.w);
        unsigned long long bd2 = pack2(b1.x, b1.y);
        unsigned long long bd3 = pack2(b1.z, b1.w);
#pragma unroll
        for (int i = 0; i < 8; i++) {
            const int ro = ((i < 4) ? i : (60 + i)) * LDIM;  // 60+i = 64+(i-4)
            unsigned long long ad = pack_dup(l0[ro + k]);
            ffma2(acc[i][0], ad, bd0);
            ffma2(acc[i][1], ad, bd1);
            ffma2(acc[i][2], ad, bd2);
            ffma2(acc[i][3], ad, bd3);
        }
    }

    __syncthreads();  // all reads of L complete before (possibly aliased) writes

#pragma unroll
    for (int i = 0; i < 8; i++) {
        const int r = (i < 4) ? (4 * ty + i) : (64 + 4 * ty + (i - 4));
        float* orow = O + r * LDIM;
#pragma unroll
        for (int h = 0; h < 2; h++) {
            const int cbase = (h == 0) ? (4 * tx) : (64 + 4 * tx);
            float2 p0 = unpack2(acc[i][2 * h]);
            float2 p1 = unpack2(acc[i][2 * h + 1]);
            float v0 = p0.x, v1 = p0.y, v2 = p1.x, v3 = p1.y;
            if (TWO_I_MINUS) {
                v0 = ((r == cbase + 0) ? 2.0f : 0.0f) - v0;
                v1 = ((r == cbase + 1) ? 2.0f : 0.0f) - v1;
                v2 = ((r == cbase + 2) ? 2.0f : 0.0f) - v2;
                v3 = ((r == cbase + 3) ? 2.0f : 0.0f) - v3;
            }
            *(float4*)(orow + cbase) = make_float4(v0, v1, v2, v3);
        }
    }
}

extern __shared__ float smem[];

__global__ void __launch_bounds__(256, 1)
newton_schulz_inverse_kernel(const float* __restrict__ W,
                             const int* __restrict__ num_iters,
                             float* __restrict__ out) {
    float* sW = smem;
    float* sX = sW + TILE_FLOATS;
    float* sT = sX + TILE_FLOATS;
    float* red = sT + TILE_FLOATS;

    const int tid = threadIdx.x;
    const int bid = blockIdx.x;
    const float* Wg = W + (size_t)bid * 16384;

    // ---- load W (padded, float4) ----
    for (int idx = tid; idx < 4096; idx += 256) {
        int r = idx >> 5, c4 = (idx & 31) << 2;
        float4 v = *(const float4*)(Wg + r * 128 + c4);
        *(float4*)(sW + r * LDIM + c4) = v;
    }
    __syncthreads();

    // ---- norms: norminf = max row |sum|, norm1 = max col |sum| ----
    if (tid < 128) {
        float rs = 0.0f, cs = 0.0f;
        for (int c = 0; c < 128; c++) {
            rs += fabsf(sW[tid * LDIM + c]);  // row tid
            cs += fabsf(sW[c * LDIM + tid]);  // col tid
        }
        red[tid] = rs;
        red[128 + tid] = cs;
    }
    __syncthreads();
    float ninf = 0.0f, n1 = 0.0f;
    for (int t = 0; t < 128; t++) {
        ninf = fmaxf(ninf, red[t]);
        n1 = fmaxf(n1, red[128 + t]);
    }
    const float rscale = 1.0f / (n1 * ninf);

    // ---- X0 = W^T * rscale ----
    for (int idx = tid; idx < 16384; idx += 256) {
        int r = idx >> 7, c = idx & 127;
        sX[c * LDIM + r] = sW[r * LDIM + c] * rscale;
    }
    __syncthreads();

    // ---- Newton-Schulz iterations ----
    const int tx = tid & 15, ty = tid >> 4;
    const int ni = *num_iters;
    for (int it = 0; it < ni; it++) {
        gemm128<true>(sW, sX, sT, tx, ty);   // T = 2I - W @ X
        __syncthreads();
        gemm128<false>(sX, sT, sX, tx, ty);  // X = X @ T  (in-place, row-safe)
        __syncthreads();
    }

    // ---- store result ----
    float* Og = out + (size_t)bid * 16384;
    for (int idx = tid; idx < 4096; idx += 256) {
        int r = idx >> 5, c4 = (idx & 31) << 2;
        *(float4*)(Og + r * 128 + c4) = *(const float4*)(sX + r * LDIM + c4);
    }
}

extern "C" void kernel_launch(void* const* d_in, const int* in_sizes, int n_in,
                              void* d_out, int out_size) {
    const float* W = (const float*)d_in[0];
    const int* num_iters = (const int*)d_in[1];
    float* out = (float*)d_out;

    const int nmat = in_sizes[0] >> 14;  // elements / (128*128)

    cudaFuncSetAttribute(newton_schulz_inverse_kernel,
                         cudaFuncAttributeMaxDynamicSharedMemorySize, SMEM_BYTES);

    newton_schulz_inverse_kernel<<<nmat, 256, SMEM_BYTES>>>(W, num_iters, out);
}